// round 15
// baseline (speedup 1.0000x reference)
#include <cuda_runtime.h>
#include <cuda_fp16.h>
#include <mma.h>
#include <cstdint>

using namespace nvcuda;

#define N_NODES 40000
#define N_EDGES 640000
#define NUM_GRAPHS 64
#define NE_TOT (N_EDGES + N_NODES)
#define N_PAD 40960                 // zero-pad for deg
#define BUCKET 64                   // max in-degree capacity (Poisson(16)+1 << 64)

// ---------------- device scratch (referenced directly by symbol) ----------------
__device__ __half  g_bufH[N_NODES * 128];   // fp16 h (gemm out, agg gather)
__device__ __half  g_xH[N_NODES * 128];     // fp16 gemm input (x or elu(agg+b))
__device__ __half  g_bufA16[N_NODES * 32];  // fp16 h for layer 2 (32-wide)
__device__ __half  g_W0h[128 * 128];
__device__ __half  g_W1h[128 * 128];
__device__ __half  g_W2h[128 * 32];
__device__ float g_als[N_NODES * 4];
__device__ float g_ald[N_NODES * 4];
__device__ __align__(16) int g_deg[N_PAD];  // in-degree (atomic cursor)
__device__ int   g_srcs[N_NODES * BUCKET];  // fixed-stride src buckets
__device__ float g_g[NUM_GRAPHS * 32];      // pooled graph sums (atomics)
__device__ int   g_is64;                    // 1 if edge_index/batch are int64
__device__ unsigned g_done;                 // last-block counter for fused MLP

// ---------------- index helpers ----------------
__device__ __forceinline__ int load_idx(const void* p, int i, bool is64) {
    return is64 ? (int)((const long long*)p)[i] : ((const int*)p)[i];
}

// ---------------- init: zero deg/g_g/done, preset is64, sample-detect dtype ---
__global__ void k_init(const void* __restrict__ ei) {
    int i = blockIdx.x * blockDim.x + threadIdx.x;
    if (i < N_PAD) g_deg[i] = 0;
    if (i < NUM_GRAPHS * 32) g_g[i] = 0.f;
    if (i == 0) g_is64 = 1;
    if (i == 1) g_done = 0;
    if (i < 1024) {                               // sample first 1024 edges
        if (((const int*)ei)[2 * i + 1] != 0) g_is64 = 0;
    }
}

// ---------------- one-pass bucket scatter (no hist/scan) ----------------
__global__ void k_scatter(const void* __restrict__ ei) {
    int i = blockIdx.x * blockDim.x + threadIdx.x;
    if (i >= NE_TOT) return;
    const bool is64 = (g_is64 != 0);
    int s, d;
    if (i < N_EDGES) {
        s = load_idx(ei, i, is64);
        d = load_idx(ei, N_EDGES + i, is64);
    } else {
        s = d = i - N_EDGES;
    }
    if ((unsigned)d >= (unsigned)N_NODES || (unsigned)s >= (unsigned)N_NODES) return;
    int pos = atomicAdd(&g_deg[d], 1);
    if (pos < BUCKET) g_srcs[d * BUCKET + pos] = s;
}

// ---------------- fp16 prep: x + all weights in ONE kernel ----------------
__global__ void k_prep(const float* __restrict__ x, const float* __restrict__ W0,
                       const float* __restrict__ W1, const float* __restrict__ W2) {
    int i = blockIdx.x * blockDim.x + threadIdx.x;
    if (i < N_NODES * 16) {                           // 640000 uint4 slots
        const float4* x4 = reinterpret_cast<const float4*>(x);
        float4 a = x4[i * 2], b = x4[i * 2 + 1];
        __half2 h0 = __floats2half2_rn(a.x, a.y);
        __half2 h1 = __floats2half2_rn(a.z, a.w);
        __half2 h2 = __floats2half2_rn(b.x, b.y);
        __half2 h3 = __floats2half2_rn(b.z, b.w);
        uint4 pk;
        pk.x = *reinterpret_cast<uint32_t*>(&h0);
        pk.y = *reinterpret_cast<uint32_t*>(&h1);
        pk.z = *reinterpret_cast<uint32_t*>(&h2);
        pk.w = *reinterpret_cast<uint32_t*>(&h3);
        reinterpret_cast<uint4*>(g_xH)[i] = pk;
    }
    if (i < 16384) {
        g_W0h[i] = __float2half_rn(W0[i]);
        g_W1h[i] = __float2half_rn(W1[i]);
    }
    if (i < 4096) g_W2h[i] = __float2half_rn(W2[i]);
}

// ---------------- big GEMM via HMMA: [N,128]@[128,128], all-fp16 fills --------
template <int WSEL>
__global__ __launch_bounds__(256) void k_gemm128_tc(
    const float* __restrict__ a_src, const float* __restrict__ a_dst) {
    __shared__ __align__(16) char smraw[49152];
    __half* sA = reinterpret_cast<__half*>(smraw);            // [64][128] 16KB
    __half* sB = reinterpret_cast<__half*>(smraw + 16384);    // [128][128] 32KB
    float*  stg = reinterpret_cast<float*>(smraw);            // [64][128] 32KB, aliases

    const int t = threadIdx.x;
    const int rbase = blockIdx.x * 64;   // 625 blocks * 64 = 40000 exactly
    const __half* __restrict__ Wh = (WSEL == 0) ? g_W0h : g_W1h;

    const uint4* __restrict__ srcx = reinterpret_cast<const uint4*>(g_xH + (size_t)rbase * 128);
#pragma unroll
    for (int i = 0; i < 4; i++)
        reinterpret_cast<uint4*>(sA)[t + i * 256] = srcx[t + i * 256];
    const uint4* __restrict__ w4 = reinterpret_cast<const uint4*>(Wh);
#pragma unroll
    for (int i = 0; i < 8; i++)
        reinterpret_cast<uint4*>(sB)[t + i * 256] = w4[t + i * 256];
    __syncthreads();

    const int w = t >> 5;
    const int wr = (w >> 2) * 32;
    const int wc = (w & 3) * 32;

    wmma::fragment<wmma::accumulator, 16, 16, 16, float> acc[2][2];
#pragma unroll
    for (int i = 0; i < 2; i++)
#pragma unroll
        for (int j = 0; j < 2; j++) wmma::fill_fragment(acc[i][j], 0.f);

    wmma::fragment<wmma::matrix_a, 16, 16, 16, __half, wmma::row_major> af[2];
    wmma::fragment<wmma::matrix_b, 16, 16, 16, __half, wmma::row_major> bf[2];
#pragma unroll
    for (int k = 0; k < 8; k++) {
        wmma::load_matrix_sync(af[0], sA + (wr +  0) * 128 + k * 16, 128);
        wmma::load_matrix_sync(af[1], sA + (wr + 16) * 128 + k * 16, 128);
        wmma::load_matrix_sync(bf[0], sB + (k * 16) * 128 + wc +  0, 128);
        wmma::load_matrix_sync(bf[1], sB + (k * 16) * 128 + wc + 16, 128);
#pragma unroll
        for (int i = 0; i < 2; i++)
#pragma unroll
            for (int j = 0; j < 2; j++)
                wmma::mma_sync(acc[i][j], af[i], bf[j], acc[i][j]);
    }
    __syncthreads();
#pragma unroll
    for (int i = 0; i < 2; i++)
#pragma unroll
        for (int j = 0; j < 2; j++)
            wmma::store_matrix_sync(stg + (wr + i * 16) * 128 + wc + j * 16,
                                    acc[i][j], 128, wmma::mem_row_major);
    __syncthreads();

    const int cg = t & 31;
    const int rg = t >> 5;
    const int head = cg >> 3;
    const float4 as4 = reinterpret_cast<const float4*>(a_src)[head * 8 + (cg & 7)];
    const float4 ad4 = reinterpret_cast<const float4*>(a_dst)[head * 8 + (cg & 7)];
#pragma unroll
    for (int r = 0; r < 8; r++) {
        const int lrow = rg * 8 + r;
        const int row = rbase + lrow;
        float4 o = *reinterpret_cast<float4*>(stg + lrow * 128 + cg * 4);
        __half2 h01 = __floats2half2_rn(o.x, o.y);
        __half2 h23 = __floats2half2_rn(o.z, o.w);
        uint2 pk;
        pk.x = *reinterpret_cast<uint32_t*>(&h01);
        pk.y = *reinterpret_cast<uint32_t*>(&h23);
        *reinterpret_cast<uint2*>(&g_bufH[(size_t)row * 128 + cg * 4]) = pk;
        float s1 = o.x * as4.x + o.y * as4.y + o.z * as4.z + o.w * as4.w;
        float s2 = o.x * ad4.x + o.y * ad4.y + o.z * ad4.z + o.w * ad4.w;
#pragma unroll
        for (int off = 1; off < 8; off <<= 1) {
            s1 += __shfl_xor_sync(0xffffffffu, s1, off);
            s2 += __shfl_xor_sync(0xffffffffu, s2, off);
        }
        if ((cg & 7) == 0) {
            g_als[row * 4 + head] = s1;
            g_ald[row * 4 + head] = s2;
        }
    }
}

// ---------------- layer-2 GEMM via HMMA: [N,128]@[128,32], fp16 fills ---------
__global__ __launch_bounds__(256) void k_gemm32_tc(
    const float* __restrict__ a_src, const float* __restrict__ a_dst) {
    __shared__ __align__(16) char smraw[32768];
    __half* sA = reinterpret_cast<__half*>(smraw);            // [64][128] 16KB
    __half* sB = reinterpret_cast<__half*>(smraw + 16384);    // [128][32]  8KB
    float*  stg = reinterpret_cast<float*>(smraw + 24576);    // [64][32]   8KB

    const int t = threadIdx.x;
    const int rbase = blockIdx.x * 64;   // 625 blocks

    const uint4* __restrict__ srcx = reinterpret_cast<const uint4*>(g_xH + (size_t)rbase * 128);
#pragma unroll
    for (int i = 0; i < 4; i++)
        reinterpret_cast<uint4*>(sA)[t + i * 256] = srcx[t + i * 256];
    const uint4* __restrict__ w4 = reinterpret_cast<const uint4*>(g_W2h);
#pragma unroll
    for (int i = 0; i < 2; i++)
        reinterpret_cast<uint4*>(sB)[t + i * 256] = w4[t + i * 256];
    __syncthreads();

    const int w = t >> 5;
    const int wr = (w >> 1) * 16;
    const int wc = (w & 1) * 16;
    wmma::fragment<wmma::accumulator, 16, 16, 16, float> acc;
    wmma::fill_fragment(acc, 0.f);
    wmma::fragment<wmma::matrix_a, 16, 16, 16, __half, wmma::row_major> af;
    wmma::fragment<wmma::matrix_b, 16, 16, 16, __half, wmma::row_major> bf;
#pragma unroll
    for (int k = 0; k < 8; k++) {
        wmma::load_matrix_sync(af, sA + wr * 128 + k * 16, 128);
        wmma::load_matrix_sync(bf, sB + (k * 16) * 32 + wc, 32);
        wmma::mma_sync(acc, af, bf, acc);
    }
    wmma::store_matrix_sync(stg + wr * 32 + wc, acc, 32, wmma::mem_row_major);
    __syncthreads();

    const int col = t & 31;
    const int rg = t >> 5;
    const float asv = a_src[col];
    const float adv = a_dst[col];
#pragma unroll
    for (int r = 0; r < 8; r++) {
        const int lrow = rg * 8 + r;
        const int row = rbase + lrow;
        float v = stg[lrow * 32 + col];
        g_bufA16[(size_t)row * 32 + col] = __float2half_rn(v);
        float s1 = v * asv, s2 = v * adv;
#pragma unroll
        for (int o = 16; o; o >>= 1) {
            s1 += __shfl_xor_sync(0xffffffffu, s1, o);
            s2 += __shfl_xor_sync(0xffffffffu, s2, o);
        }
        if (col == 0) {
            g_als[row] = s1;
            g_ald[row] = s2;
        }
    }
}

// ---------------- GAT agg (H=4): 2 warps/node, 64 channels each ----------------
// Two-phase softmax: phase 1 computes p for 16 edges x 2 heads; phase 2 gathers.
// Per-warp trip counts uniform; warps fully independent (no combine).
__global__ __launch_bounds__(256) void k_agg4(const float* __restrict__ bnext) {
    const int gw = (blockIdx.x * blockDim.x + threadIdx.x) >> 5;  // global warp
    const int d = gw >> 1;
    if (d >= N_NODES) return;
    const int part = gw & 1;             // which 64-channel half
    const int lane = threadIdx.x & 31;
    const int beg = d * BUCKET;
    const int deg = min(g_deg[d], BUCKET);
    const int headp = part * 2 + (lane & 1);    // phase-1 head
    const int hsel  = lane >> 4;                // phase-2 head offset (0/1)

    const float aldp = g_ald[d * 4 + headp];
    float den = 0.f, acc0 = 0.f, acc1 = 0.f;
    const __half* __restrict__ hrow = g_bufH + part * 64 + lane * 2;

    for (int base = 0; base < deg; base += 16) {
        const int jj = base + (lane >> 1);
        int sv = 0;
        float p = 0.f;
        if (jj < deg) {
            sv = g_srcs[beg + jj];
            float e = g_als[sv * 4 + headp] + aldp;
            e = fmaxf(e, 0.2f * e);
            e = fminf(e, 60.f);
            p = __expf(e);
        }
        const int cnt = min(16, deg - base);
        if (cnt == 16) {
#pragma unroll
            for (int k = 0; k < 16; k++) {
                const int   s  = __shfl_sync(0xffffffffu, sv, k * 2);
                const float pk = __shfl_sync(0xffffffffu, p,  k * 2 + hsel);
                den += pk;
                float2 f = __half22float2(*reinterpret_cast<const __half2*>(hrow + (size_t)s * 128));
                acc0 += pk * f.x;
                acc1 += pk * f.y;
            }
        } else {
            for (int k = 0; k < cnt; k++) {
                const int   s  = __shfl_sync(0xffffffffu, sv, k * 2);
                const float pk = __shfl_sync(0xffffffffu, p,  k * 2 + hsel);
                den += pk;
                float2 f = __half22float2(*reinterpret_cast<const __half2*>(hrow + (size_t)s * 128));
                acc0 += pk * f.x;
                acc1 += pk * f.y;
            }
        }
    }
    const float inv = 1.f / fmaxf(den, 1e-16f);
    const float2 bn = *reinterpret_cast<const float2*>(bnext + part * 64 + lane * 2);
    float v0 = acc0 * inv + bn.x;
    float v1 = acc1 * inv + bn.y;
    v0 = v0 > 0.f ? v0 : expm1f(v0);
    v1 = v1 > 0.f ? v1 : expm1f(v1);
    __half2 h = __floats2half2_rn(v0, v1);
    *reinterpret_cast<__half2*>(&g_xH[(size_t)d * 128 + part * 64 + lane * 2]) = h;
}

// ---------------- GAT agg (H=1) + ELU + pool sums + FUSED last-block MLP ------
__global__ __launch_bounds__(256) void k_agg1(
    const void* __restrict__ batch, const float* __restrict__ b2,
    const float* __restrict__ w1, const float* __restrict__ b1,
    const float* __restrict__ w2, const float* __restrict__ b2o,
    float* __restrict__ out) {
    const int t = threadIdx.x;
    int d = (blockIdx.x * blockDim.x + t) >> 5;   // grid = 5000 blocks exactly
    const int lane = t & 31;
    const int beg = d * BUCKET;
    const int deg = min(g_deg[d], BUCKET);

    const float aldh = g_ald[d];
    float den = 0.f, acc = 0.f;
    const __half* __restrict__ hcol = g_bufA16 + lane;

    for (int base = 0; base < deg; base += 32) {
        const int jj = base + lane;
        int sv = 0;
        float p = 0.f;
        if (jj < deg) {
            sv = g_srcs[beg + jj];
            float e = g_als[sv] + aldh;
            e = fmaxf(e, 0.2f * e);
            e = fminf(e, 60.f);
            p = __expf(e);
        }
        const int cnt = min(32, deg - base);
        for (int k = 0; k < cnt; k++) {
            const int   s  = __shfl_sync(0xffffffffu, sv, k);
            const float pk = __shfl_sync(0xffffffffu, p,  k);
            den += pk;
            acc += pk * __half2float(hcol[(size_t)s * 32]);
        }
    }
    float v = acc / fmaxf(den, 1e-16f);
    v += b2[lane];
    v = v > 0.f ? v : expm1f(v);
    const bool is64 = (g_is64 != 0);
    const int bd = load_idx(batch, d, is64);
    atomicAdd(&g_g[bd * 32 + lane], v);

    // ---- last block runs the MLP ----
    __shared__ bool s_last;
    __threadfence();
    __syncthreads();
    if (t == 0) s_last = (atomicAdd(&g_done, 1u) == gridDim.x - 1);
    __syncthreads();
    if (!s_last) return;

    __shared__ int cnts[NUM_GRAPHS];
    __shared__ float gvs[2][32], t1s[2][128];
    if (t < NUM_GRAPHS) {
        int lo = 0, hi = N_NODES;
        while (lo < hi) { int mid = (lo + hi) >> 1;
            if (load_idx(batch, mid, is64) < t) lo = mid + 1; else hi = mid; }
        int start = lo;
        lo = start; hi = N_NODES;
        while (lo < hi) { int mid = (lo + hi) >> 1;
            if (load_idx(batch, mid, is64) < t + 1) lo = mid + 1; else hi = mid; }
        cnts[t] = lo - start;
    }
    __syncthreads();
    const int gpart = t >> 7;          // 0 or 1: two graphs per iteration
    const int col = t & 127;
    for (int it = 0; it < NUM_GRAPHS / 2; it++) {
        const int gi = it * 2 + gpart;
        if (col < 32) gvs[gpart][col] = g_g[gi * 32 + col] / fmaxf((float)cnts[gi], 1.f);
        __syncthreads();
        float a = b1[col];
#pragma unroll 8
        for (int c = 0; c < 32; c++) a += gvs[gpart][c] * w1[c * 128 + col];
        t1s[gpart][col] = fmaxf(a, 0.f);
        __syncthreads();
        if (col < 8) {
            float o = b2o[col];
#pragma unroll 8
            for (int j = 0; j < 128; j++) o += t1s[gpart][j] * w2[j * 8 + col];
            out[gi * 8 + col] = o;
        }
        __syncthreads();
    }
}

// ---------------- launch ----------------
extern "C" void kernel_launch(void* const* d_in, const int* in_sizes, int n_in,
                              void* d_out, int out_size) {
    const float* x     = (const float*)d_in[0];
    const void*  ei    = d_in[1];
    const void*  batch = d_in[2];
    const float* W0  = (const float*)d_in[3];
    const float* as0 = (const float*)d_in[4];
    const float* ad0 = (const float*)d_in[5];
    const float* b0  = (const float*)d_in[6];
    const float* W1  = (const float*)d_in[7];
    const float* as1 = (const float*)d_in[8];
    const float* ad1 = (const float*)d_in[9];
    const float* b1  = (const float*)d_in[10];
    const float* W2  = (const float*)d_in[11];
    const float* as2 = (const float*)d_in[12];
    const float* ad2 = (const float*)d_in[13];
    const float* b2  = (const float*)d_in[14];
    const float* l1w = (const float*)d_in[15];
    const float* l1b = (const float*)d_in[16];
    const float* l2w = (const float*)d_in[17];
    const float* l2b = (const float*)d_in[18];

    const int eblk = (NE_TOT + 255) / 256;
    const int nblk = (N_PAD + 255) / 256;
    const int gemm_blocks = N_NODES / 64;                 // 625, exact
    const int agg4_blocks = (N_NODES * 2 + 7) / 8;        // 10000 (2 warps/node)
    const int agg1_blocks = N_NODES / 8;                  // 5000, exact
    const int prep_blocks = (N_NODES * 16 + 255) / 256;   // 2500

    // fork-join resources, created once on the (uncaptured) correctness call
    static cudaStream_t s2 = nullptr;
    static cudaEvent_t evFork = nullptr, evJoin = nullptr;
    if (s2 == nullptr) {
        cudaStreamCreateWithFlags(&s2, cudaStreamNonBlocking);
        cudaEventCreateWithFlags(&evFork, cudaEventDisableTiming);
        cudaEventCreateWithFlags(&evJoin, cudaEventDisableTiming);
    }

    // fork: bucket build on s2
    cudaEventRecord(evFork, 0);
    cudaStreamWaitEvent(s2, evFork, 0);
    k_init<<<nblk, 256, 0, s2>>>(ei);
    k_scatter<<<eblk, 256, 0, s2>>>(ei);
    cudaEventRecord(evJoin, s2);

    // main: fused fp16 prep + gemm0 (overlaps the bucket build)
    k_prep<<<prep_blocks, 256>>>(x, W0, W1, W2);
    k_gemm128_tc<0><<<gemm_blocks, 256>>>(as0, ad0);

    cudaStreamWaitEvent(0, evJoin, 0);       // join before first aggregation

    k_agg4<<<agg4_blocks, 256>>>(b0);        // -> elu(out+b0) fp16 in g_xH
    k_gemm128_tc<1><<<gemm_blocks, 256>>>(as1, ad1);
    k_agg4<<<agg4_blocks, 256>>>(b1);        // -> elu(out+b1) fp16 in g_xH
    k_gemm32_tc<<<gemm_blocks, 256>>>(as2, ad2);
    // agg1 + pool + fused last-block MLP
    k_agg1<<<agg1_blocks, 256>>>(batch, b2, l1w, l1b, l2w, l2b, (float*)d_out);
}

// round 16
// speedup vs baseline: 1.9164x; 1.9164x over previous
#include <cuda_runtime.h>
#include <cuda_fp16.h>
#include <mma.h>
#include <cstdint>

using namespace nvcuda;

#define N_NODES 40000
#define N_EDGES 640000
#define NUM_GRAPHS 64
#define NE_TOT (N_EDGES + N_NODES)
#define N_PAD 40960                 // zero-pad for deg
#define BUCKET 64                   // max in-degree capacity (Poisson(16)+1 << 64)

#define LDA 136                     // padded smem stride (halves): 272B, conflict-free
#define LDS_STG 132                 // padded staging stride (floats): 528B, conflict-free
#define GEMM128_SMEM (64 * LDA * 2 + 128 * LDA * 2)   // 17408 + 34816 = 52224

// ---------------- device scratch (referenced directly by symbol) ----------------
__device__ __half  g_bufH[N_NODES * 128];   // fp16 h (gemm out, agg gather)
__device__ __half  g_xH[N_NODES * 128];     // fp16 gemm input (x or elu(agg+b))
__device__ __half  g_bufA16[N_NODES * 32];  // fp16 h for layer 2 (32-wide)
__device__ __half  g_W0h[128 * 128];
__device__ __half  g_W1h[128 * 128];
__device__ __half  g_W2h[128 * 32];
__device__ float g_als[N_NODES * 4];
__device__ float g_ald[N_NODES * 4];
__device__ __align__(16) int g_deg[N_PAD];  // in-degree (atomic cursor)
__device__ int   g_srcs[N_NODES * BUCKET];  // fixed-stride src buckets
__device__ float g_g[NUM_GRAPHS * 32];      // pooled graph sums (atomics)
__device__ int   g_is64;                    // 1 if edge_index/batch are int64

// ---------------- index helpers ----------------
__device__ __forceinline__ int load_idx(const void* p, int i, bool is64) {
    return is64 ? (int)((const long long*)p)[i] : ((const int*)p)[i];
}

// ---------------- init: zero deg/g_g, preset is64, sample-detect dtype --------
__global__ void k_init(const void* __restrict__ ei) {
    int i = blockIdx.x * blockDim.x + threadIdx.x;
    if (i < N_PAD) g_deg[i] = 0;
    if (i < NUM_GRAPHS * 32) g_g[i] = 0.f;
    if (i == 0) g_is64 = 1;
    if (i < 1024) {                               // sample first 1024 edges
        if (((const int*)ei)[2 * i + 1] != 0) g_is64 = 0;
    }
}

// ---------------- one-pass bucket scatter (no hist/scan) ----------------
__global__ void k_scatter(const void* __restrict__ ei) {
    int i = blockIdx.x * blockDim.x + threadIdx.x;
    if (i >= NE_TOT) return;
    const bool is64 = (g_is64 != 0);
    int s, d;
    if (i < N_EDGES) {
        s = load_idx(ei, i, is64);
        d = load_idx(ei, N_EDGES + i, is64);
    } else {
        s = d = i - N_EDGES;
    }
    if ((unsigned)d >= (unsigned)N_NODES || (unsigned)s >= (unsigned)N_NODES) return;
    int pos = atomicAdd(&g_deg[d], 1);
    if (pos < BUCKET) g_srcs[d * BUCKET + pos] = s;
}

// ---------------- fp16 prep: x + all weights in ONE kernel ----------------
__global__ void k_prep(const float* __restrict__ x, const float* __restrict__ W0,
                       const float* __restrict__ W1, const float* __restrict__ W2) {
    int i = blockIdx.x * blockDim.x + threadIdx.x;
    if (i < N_NODES * 16) {                           // 640000 uint4 slots
        const float4* x4 = reinterpret_cast<const float4*>(x);
        float4 a = x4[i * 2], b = x4[i * 2 + 1];
        __half2 h0 = __floats2half2_rn(a.x, a.y);
        __half2 h1 = __floats2half2_rn(a.z, a.w);
        __half2 h2 = __floats2half2_rn(b.x, b.y);
        __half2 h3 = __floats2half2_rn(b.z, b.w);
        uint4 pk;
        pk.x = *reinterpret_cast<uint32_t*>(&h0);
        pk.y = *reinterpret_cast<uint32_t*>(&h1);
        pk.z = *reinterpret_cast<uint32_t*>(&h2);
        pk.w = *reinterpret_cast<uint32_t*>(&h3);
        reinterpret_cast<uint4*>(g_xH)[i] = pk;
    }
    if (i < 16384) {
        g_W0h[i] = __float2half_rn(W0[i]);
        g_W1h[i] = __float2half_rn(W1[i]);
    }
    if (i < 4096) g_W2h[i] = __float2half_rn(W2[i]);
}

// ---------------- big GEMM via HMMA: [N,128]@[128,128], padded smem ----------
template <int WSEL>
__global__ __launch_bounds__(256) void k_gemm128_tc(
    const float* __restrict__ a_src, const float* __restrict__ a_dst) {
    extern __shared__ __align__(16) char smraw[];
    __half* sA = reinterpret_cast<__half*>(smraw);              // [64][LDA]
    __half* sB = reinterpret_cast<__half*>(smraw + 64 * LDA * 2);  // [128][LDA]
    float*  stg = reinterpret_cast<float*>(smraw);              // [64][LDS_STG], aliases

    const int t = threadIdx.x;
    const int rbase = blockIdx.x * 64;   // 625 blocks * 64 = 40000 exactly
    const __half* __restrict__ Wh = (WSEL == 0) ? g_W0h : g_W1h;

    // fills: row-padded fp16 copies (16 uint4 per 128-half row)
    const uint4* __restrict__ srcx = reinterpret_cast<const uint4*>(g_xH + (size_t)rbase * 128);
#pragma unroll
    for (int i = 0; i < 4; i++) {
        int slot = t + i * 256;                     // 1024 slots
        int row = slot >> 4, col = slot & 15;
        reinterpret_cast<uint4*>(sA + row * LDA)[col] = srcx[slot];
    }
    const uint4* __restrict__ w4 = reinterpret_cast<const uint4*>(Wh);
#pragma unroll
    for (int i = 0; i < 8; i++) {
        int slot = t + i * 256;                     // 2048 slots
        int row = slot >> 4, col = slot & 15;
        reinterpret_cast<uint4*>(sB + row * LDA)[col] = w4[slot];
    }
    __syncthreads();

    const int w = t >> 5;
    const int wr = (w >> 2) * 32;
    const int wc = (w & 3) * 32;

    wmma::fragment<wmma::accumulator, 16, 16, 16, float> acc[2][2];
#pragma unroll
    for (int i = 0; i < 2; i++)
#pragma unroll
        for (int j = 0; j < 2; j++) wmma::fill_fragment(acc[i][j], 0.f);

    wmma::fragment<wmma::matrix_a, 16, 16, 16, __half, wmma::row_major> af[2];
    wmma::fragment<wmma::matrix_b, 16, 16, 16, __half, wmma::row_major> bf[2];
#pragma unroll
    for (int k = 0; k < 8; k++) {
        wmma::load_matrix_sync(af[0], sA + (wr +  0) * LDA + k * 16, LDA);
        wmma::load_matrix_sync(af[1], sA + (wr + 16) * LDA + k * 16, LDA);
        wmma::load_matrix_sync(bf[0], sB + (k * 16) * LDA + wc +  0, LDA);
        wmma::load_matrix_sync(bf[1], sB + (k * 16) * LDA + wc + 16, LDA);
#pragma unroll
        for (int i = 0; i < 2; i++)
#pragma unroll
            for (int j = 0; j < 2; j++)
                wmma::mma_sync(acc[i][j], af[i], bf[j], acc[i][j]);
    }
    __syncthreads();
#pragma unroll
    for (int i = 0; i < 2; i++)
#pragma unroll
        for (int j = 0; j < 2; j++)
            wmma::store_matrix_sync(stg + (wr + i * 16) * LDS_STG + wc + j * 16,
                                    acc[i][j], LDS_STG, wmma::mem_row_major);
    __syncthreads();

    const int cg = t & 31;
    const int rg = t >> 5;
    const int head = cg >> 3;
    const float4 as4 = reinterpret_cast<const float4*>(a_src)[head * 8 + (cg & 7)];
    const float4 ad4 = reinterpret_cast<const float4*>(a_dst)[head * 8 + (cg & 7)];
#pragma unroll
    for (int r = 0; r < 8; r++) {
        const int lrow = rg * 8 + r;
        const int row = rbase + lrow;
        float4 o = *reinterpret_cast<float4*>(stg + lrow * LDS_STG + cg * 4);
        __half2 h01 = __floats2half2_rn(o.x, o.y);
        __half2 h23 = __floats2half2_rn(o.z, o.w);
        uint2 pk;
        pk.x = *reinterpret_cast<uint32_t*>(&h01);
        pk.y = *reinterpret_cast<uint32_t*>(&h23);
        *reinterpret_cast<uint2*>(&g_bufH[(size_t)row * 128 + cg * 4]) = pk;
        float s1 = o.x * as4.x + o.y * as4.y + o.z * as4.z + o.w * as4.w;
        float s2 = o.x * ad4.x + o.y * ad4.y + o.z * ad4.z + o.w * ad4.w;
#pragma unroll
        for (int off = 1; off < 8; off <<= 1) {
            s1 += __shfl_xor_sync(0xffffffffu, s1, off);
            s2 += __shfl_xor_sync(0xffffffffu, s2, off);
        }
        if ((cg & 7) == 0) {
            g_als[row * 4 + head] = s1;
            g_ald[row * 4 + head] = s2;
        }
    }
}

// ---------------- layer-2 GEMM via HMMA: [N,128]@[128,32], padded smem --------
#define LDB32 40                    // padded B stride: 80B, conflict-free
#define LDS32 36                    // padded staging stride (floats)
__global__ __launch_bounds__(256) void k_gemm32_tc(
    const float* __restrict__ a_src, const float* __restrict__ a_dst) {
    __shared__ __align__(16) char smraw[64 * LDA * 2 + 128 * LDB32 * 2 + 64 * LDS32 * 4];
    __half* sA = reinterpret_cast<__half*>(smraw);                       // [64][LDA]
    __half* sB = reinterpret_cast<__half*>(smraw + 64 * LDA * 2);        // [128][LDB32]
    float*  stg = reinterpret_cast<float*>(smraw + 64 * LDA * 2 + 128 * LDB32 * 2);

    const int t = threadIdx.x;
    const int rbase = blockIdx.x * 64;   // 625 blocks

    const uint4* __restrict__ srcx = reinterpret_cast<const uint4*>(g_xH + (size_t)rbase * 128);
#pragma unroll
    for (int i = 0; i < 4; i++) {
        int slot = t + i * 256;
        int row = slot >> 4, col = slot & 15;
        reinterpret_cast<uint4*>(sA + row * LDA)[col] = srcx[slot];
    }
    const uint4* __restrict__ w4 = reinterpret_cast<const uint4*>(g_W2h);
#pragma unroll
    for (int i = 0; i < 2; i++) {
        int slot = t + i * 256;                     // 512 slots: 128 rows x 4
        int row = slot >> 2, col = slot & 3;
        reinterpret_cast<uint4*>(sB + row * LDB32)[col] = w4[slot];
    }
    __syncthreads();

    const int w = t >> 5;
    const int wr = (w >> 1) * 16;
    const int wc = (w & 1) * 16;
    wmma::fragment<wmma::accumulator, 16, 16, 16, float> acc;
    wmma::fill_fragment(acc, 0.f);
    wmma::fragment<wmma::matrix_a, 16, 16, 16, __half, wmma::row_major> af;
    wmma::fragment<wmma::matrix_b, 16, 16, 16, __half, wmma::row_major> bf;
#pragma unroll
    for (int k = 0; k < 8; k++) {
        wmma::load_matrix_sync(af, sA + wr * LDA + k * 16, LDA);
        wmma::load_matrix_sync(bf, sB + (k * 16) * LDB32 + wc, LDB32);
        wmma::mma_sync(acc, af, bf, acc);
    }
    wmma::store_matrix_sync(stg + wr * LDS32 + wc, acc, LDS32, wmma::mem_row_major);
    __syncthreads();

    const int col = t & 31;
    const int rg = t >> 5;
    const float asv = a_src[col];
    const float adv = a_dst[col];
#pragma unroll
    for (int r = 0; r < 8; r++) {
        const int lrow = rg * 8 + r;
        const int row = rbase + lrow;
        float v = stg[lrow * LDS32 + col];
        g_bufA16[(size_t)row * 32 + col] = __float2half_rn(v);
        float s1 = v * asv, s2 = v * adv;
#pragma unroll
        for (int o = 16; o; o >>= 1) {
            s1 += __shfl_xor_sync(0xffffffffu, s1, o);
            s2 += __shfl_xor_sync(0xffffffffu, s2, o);
        }
        if (col == 0) {
            g_als[row] = s1;
            g_ald[row] = s2;
        }
    }
}

// ---------------- GAT agg (H=4): two-phase softmax + fused ELU+bias, fp16 out -
// (R14 version: one warp per node — proven fastest form)
__global__ __launch_bounds__(256) void k_agg4(const float* __restrict__ bnext) {
    int d = (blockIdx.x * blockDim.x + threadIdx.x) >> 5;
    if (d >= N_NODES) return;
    const int lane = threadIdx.x & 31;
    const int head = lane >> 3;
    const int beg = d * BUCKET;
    const int deg = min(g_deg[d], BUCKET);

    const float aldp = g_ald[d * 4 + (lane & 3)];   // phase-1 head = lane&3
    float den = 0.f;
    float acc0 = 0.f, acc1 = 0.f, acc2 = 0.f, acc3 = 0.f;
    const __half* __restrict__ hrow = g_bufH + lane * 4;

    for (int base = 0; base < deg; base += 8) {
        const int jj = base + (lane >> 2);
        int sv = 0;
        float p = 0.f;
        if (jj < deg) {
            sv = g_srcs[beg + jj];
            float e = g_als[sv * 4 + (lane & 3)] + aldp;
            e = fmaxf(e, 0.2f * e);
            e = fminf(e, 60.f);
            p = __expf(e);
        }
        const int cnt = min(8, deg - base);
        if (cnt == 8) {
#pragma unroll
            for (int k = 0; k < 8; k++) {
                const int   s  = __shfl_sync(0xffffffffu, sv, k * 4);
                const float pk = __shfl_sync(0xffffffffu, p,  k * 4 + head);
                den += pk;
                uint2 raw = *reinterpret_cast<const uint2*>(hrow + (size_t)s * 128);
                float2 f01 = __half22float2(*reinterpret_cast<__half2*>(&raw.x));
                float2 f23 = __half22float2(*reinterpret_cast<__half2*>(&raw.y));
                acc0 += pk * f01.x; acc1 += pk * f01.y;
                acc2 += pk * f23.x; acc3 += pk * f23.y;
            }
        } else {
            for (int k = 0; k < cnt; k++) {
                const int   s  = __shfl_sync(0xffffffffu, sv, k * 4);
                const float pk = __shfl_sync(0xffffffffu, p,  k * 4 + head);
                den += pk;
                uint2 raw = *reinterpret_cast<const uint2*>(hrow + (size_t)s * 128);
                float2 f01 = __half22float2(*reinterpret_cast<__half2*>(&raw.x));
                float2 f23 = __half22float2(*reinterpret_cast<__half2*>(&raw.y));
                acc0 += pk * f01.x; acc1 += pk * f01.y;
                acc2 += pk * f23.x; acc3 += pk * f23.y;
            }
        }
    }
    const float inv = 1.f / fmaxf(den, 1e-16f);
    const float4 bn = *reinterpret_cast<const float4*>(bnext + lane * 4);
    float v0 = acc0 * inv + bn.x;
    float v1 = acc1 * inv + bn.y;
    float v2 = acc2 * inv + bn.z;
    float v3 = acc3 * inv + bn.w;
    v0 = v0 > 0.f ? v0 : expm1f(v0);
    v1 = v1 > 0.f ? v1 : expm1f(v1);
    v2 = v2 > 0.f ? v2 : expm1f(v2);
    v3 = v3 > 0.f ? v3 : expm1f(v3);
    __half2 h01 = __floats2half2_rn(v0, v1);
    __half2 h23 = __floats2half2_rn(v2, v3);
    uint2 pk;
    pk.x = *reinterpret_cast<uint32_t*>(&h01);
    pk.y = *reinterpret_cast<uint32_t*>(&h23);
    *reinterpret_cast<uint2*>(&g_xH[(size_t)d * 128 + lane * 4]) = pk;
}

// ---------------- GAT agg (H=1): two-phase + ELU + pool sums ----------------
__global__ __launch_bounds__(256) void k_agg1(
    const void* __restrict__ batch, const float* __restrict__ b2) {
    int d = (blockIdx.x * blockDim.x + threadIdx.x) >> 5;
    if (d >= N_NODES) return;
    const int lane = threadIdx.x & 31;
    const int beg = d * BUCKET;
    const int deg = min(g_deg[d], BUCKET);

    const float aldh = g_ald[d];
    float den = 0.f, acc = 0.f;
    const __half* __restrict__ hcol = g_bufA16 + lane;

    for (int base = 0; base < deg; base += 32) {
        const int jj = base + lane;
        int sv = 0;
        float p = 0.f;
        if (jj < deg) {
            sv = g_srcs[beg + jj];
            float e = g_als[sv] + aldh;
            e = fmaxf(e, 0.2f * e);
            e = fminf(e, 60.f);
            p = __expf(e);
        }
        const int cnt = min(32, deg - base);
        for (int k = 0; k < cnt; k++) {
            const int   s  = __shfl_sync(0xffffffffu, sv, k);
            const float pk = __shfl_sync(0xffffffffu, p,  k);
            den += pk;
            acc += pk * __half2float(hcol[(size_t)s * 32]);
        }
    }
    float v = acc / fmaxf(den, 1e-16f);
    v += b2[lane];
    v = v > 0.f ? v : expm1f(v);
    const int bd = load_idx(batch, d, g_is64 != 0);
    atomicAdd(&g_g[bd * 32 + lane], v);
}

// ---------------- final MLP: relu((g/cnt)@W1+b1)@W2+b2 ----------------
__global__ __launch_bounds__(128) void k_mlp(
    const void* __restrict__ batch,
    const float* __restrict__ w1, const float* __restrict__ b1,
    const float* __restrict__ w2, const float* __restrict__ b2o,
    float* __restrict__ out) {
    const int gi = blockIdx.x;
    const int t = threadIdx.x;
    __shared__ float gv[32], t1[128];
    __shared__ int cnt_s;
    if (t == 0) {
        const bool is64 = (g_is64 != 0);
        int lo = 0, hi = N_NODES;
        while (lo < hi) { int mid = (lo + hi) >> 1;
            if (load_idx(batch, mid, is64) < gi) lo = mid + 1; else hi = mid; }
        int start = lo;
        lo = start; hi = N_NODES;
        while (lo < hi) { int mid = (lo + hi) >> 1;
            if (load_idx(batch, mid, is64) < gi + 1) lo = mid + 1; else hi = mid; }
        cnt_s = lo - start;
    }
    __syncthreads();
    if (t < 32) gv[t] = g_g[gi * 32 + t] / fmaxf((float)cnt_s, 1.f);
    __syncthreads();
    float acc = b1[t];
#pragma unroll
    for (int c = 0; c < 32; c++) acc += gv[c] * w1[c * 128 + t];
    t1[t] = fmaxf(acc, 0.f);
    __syncthreads();
    if (t < 8) {
        float o = b2o[t];
#pragma unroll 8
        for (int j = 0; j < 128; j++) o += t1[j] * w2[j * 8 + t];
        out[gi * 8 + t] = o;
    }
}

// ---------------- launch ----------------
extern "C" void kernel_launch(void* const* d_in, const int* in_sizes, int n_in,
                              void* d_out, int out_size) {
    const float* x     = (const float*)d_in[0];
    const void*  ei    = d_in[1];
    const void*  batch = d_in[2];
    const float* W0  = (const float*)d_in[3];
    const float* as0 = (const float*)d_in[4];
    const float* ad0 = (const float*)d_in[5];
    const float* b0  = (const float*)d_in[6];
    const float* W1  = (const float*)d_in[7];
    const float* as1 = (const float*)d_in[8];
    const float* ad1 = (const float*)d_in[9];
    const float* b1  = (const float*)d_in[10];
    const float* W2  = (const float*)d_in[11];
    const float* as2 = (const float*)d_in[12];
    const float* ad2 = (const float*)d_in[13];
    const float* b2  = (const float*)d_in[14];
    const float* l1w = (const float*)d_in[15];
    const float* l1b = (const float*)d_in[16];
    const float* l2w = (const float*)d_in[17];
    const float* l2b = (const float*)d_in[18];

    const int eblk = (NE_TOT + 255) / 256;
    const int nblk = (N_PAD + 255) / 256;
    const int gemm_blocks = N_NODES / 64;                 // 625, exact
    const int agg_blocks  = (N_NODES + 7) / 8;            // 5000
    const int prep_blocks = (N_NODES * 16 + 255) / 256;   // 2500

    // one-time resources (created on the uncaptured correctness call)
    static cudaStream_t s2 = nullptr;
    static cudaEvent_t evFork = nullptr, evJoin = nullptr;
    if (s2 == nullptr) {
        cudaStreamCreateWithFlags(&s2, cudaStreamNonBlocking);
        cudaEventCreateWithFlags(&evFork, cudaEventDisableTiming);
        cudaEventCreateWithFlags(&evJoin, cudaEventDisableTiming);
        cudaFuncSetAttribute(k_gemm128_tc<0>,
            cudaFuncAttributeMaxDynamicSharedMemorySize, GEMM128_SMEM);
        cudaFuncSetAttribute(k_gemm128_tc<1>,
            cudaFuncAttributeMaxDynamicSharedMemorySize, GEMM128_SMEM);
    }

    // fork: bucket build on s2
    cudaEventRecord(evFork, 0);
    cudaStreamWaitEvent(s2, evFork, 0);
    k_init<<<nblk, 256, 0, s2>>>(ei);
    k_scatter<<<eblk, 256, 0, s2>>>(ei);
    cudaEventRecord(evJoin, s2);

    // main: fused fp16 prep + gemm0 (overlaps the bucket build)
    k_prep<<<prep_blocks, 256>>>(x, W0, W1, W2);
    k_gemm128_tc<0><<<gemm_blocks, 256, GEMM128_SMEM>>>(as0, ad0);

    cudaStreamWaitEvent(0, evJoin, 0);       // join before first aggregation

    k_agg4<<<agg_blocks, 256>>>(b0);         // -> elu(out+b0) fp16 in g_xH
    k_gemm128_tc<1><<<gemm_blocks, 256, GEMM128_SMEM>>>(as1, ad1);
    k_agg4<<<agg_blocks, 256>>>(b1);         // -> elu(out+b1) fp16 in g_xH
    k_gemm32_tc<<<gemm_blocks, 256>>>(as2, ad2);
    k_agg1<<<agg_blocks, 256>>>(batch, b2);

    // MLP (divides pooled sums by counts)
    k_mlp<<<NUM_GRAPHS, 128>>>(batch, l1w, l1b, l2w, l2b, (float*)d_out);
}